// round 5
// baseline (speedup 1.0000x reference)
#include <cuda_runtime.h>
#include <cuda_bf16.h>
#include <cstdint>

// Problem constants
#define E1C   600000
#define E2C   300000
#define N1C   100000
#define N2C   20000

// ---------------- scratch (device globals; no allocation allowed) ----------------
__device__ int    g_rowptr1[N1C + 1];
__device__ int    g_cursor1[N1C + 1];
__device__ int    g_rowptr2[N2C + 1];
__device__ int    g_cursor2[N2C + 1];
__device__ int    g_bs1[64];
__device__ int    g_bs2[64];
__device__ int    g_end1[E1C];          // packed sorted: gather index
__device__ float4 g_ew1[E1C];           // packed sorted: comp[et]*norm per basis
__device__ int    g_end2[E2C];
__device__ float4 g_ew2[E2C];
__device__ float  g_h[(size_t)N1C * 64];   // layer-1 output (25.6 MB)

// ---------------- packed f32x2 FMA (FFMA2 on sm_103a) ----------------
__device__ __forceinline__ float2 ffma2(float2 a, float2 b, float2 c) {
    float2 d;
    asm("fma.rn.f32x2 %0, %1, %2, %3;"
        : "=l"(reinterpret_cast<unsigned long long&>(d))
        : "l"(reinterpret_cast<unsigned long long&>(a)),
          "l"(reinterpret_cast<unsigned long long&>(b)),
          "l"(reinterpret_cast<unsigned long long&>(c)));
    return d;
}

// ---------------- counting-sort kernels ----------------
__global__ void k_zero(int* __restrict__ c1, int n1, int* __restrict__ c2, int n2) {
    int i = blockIdx.x * blockDim.x + threadIdx.x;
    if (i <= n1) c1[i] = 0;
    if (i <= n2) c2[i] = 0;
}

__global__ void k_hist(const int* __restrict__ dst1, const int* __restrict__ dst2,
                       int* __restrict__ c1, int* __restrict__ c2) {
    int i = blockIdx.x * blockDim.x + threadIdx.x;
    if (i < E1C) {
        atomicAdd(&c1[__ldg(dst1 + i)], 1);
    } else if (i < E1C + E2C) {
        atomicAdd(&c2[__ldg(dst2 + i - E1C)], 1);
    }
}

// per-block exclusive scan over 2048-element chunks; both layers in one launch
__global__ void k_scan_local2(const int* __restrict__ cntA, int* __restrict__ exclA,
                              int* __restrict__ bsA, int nA, int nbA,
                              const int* __restrict__ cntB, int* __restrict__ exclB,
                              int* __restrict__ bsB, int nB) {
    const int t = threadIdx.x;
    const bool isA = (blockIdx.x < (unsigned)nbA);
    const int bid = isA ? blockIdx.x : blockIdx.x - nbA;
    const int* cnt = isA ? cntA : cntB;
    int* excl = isA ? exclA : exclB;
    int* bsums = isA ? bsA : bsB;
    const int n = isA ? nA : nB;

    const int base = bid * 2048 + t * 8;
    int v[8], pre[8], s = 0;
#pragma unroll
    for (int j = 0; j < 8; j++) {
        int idx = base + j;
        v[j] = (idx < n) ? cnt[idx] : 0;
        pre[j] = s;
        s += v[j];
    }
    int lane = t & 31, wid = t >> 5;
    int inc = s;
#pragma unroll
    for (int off = 1; off < 32; off <<= 1) {
        int y = __shfl_up_sync(0xffffffffu, inc, off);
        if (lane >= off) inc += y;
    }
    __shared__ int wsum[8];
    __shared__ int wexcl[8];
    if (lane == 31) wsum[wid] = inc;
    __syncthreads();
    if (t == 0) {
        int run = 0;
        for (int w = 0; w < 8; w++) { wexcl[w] = run; run += wsum[w]; }
    }
    __syncthreads();
    int texcl = wexcl[wid] + inc - s;
#pragma unroll
    for (int j = 0; j < 8; j++) {
        int idx = base + j;
        if (idx < n) excl[idx] = texcl + pre[j];
    }
    if (t == 255) bsums[bid] = wexcl[7] + wsum[7];
}

// one block scans each bsums array (<=64 entries)
__global__ void k_scan_bsums2(int* __restrict__ bsA, int nA,
                              int* __restrict__ bsB, int nB) {
    __shared__ int sh[64];
    int t = threadIdx.x;
    int* bs = (blockIdx.x == 0) ? bsA : bsB;
    int nb  = (blockIdx.x == 0) ? nA : nB;
    int v = (t < nb) ? bs[t] : 0;
    int x = v;
    sh[t] = x;
    __syncthreads();
    for (int off = 1; off < 64; off <<= 1) {
        int y = (t >= off) ? sh[t - off] : 0;
        __syncthreads();
        x += y;
        sh[t] = x;
        __syncthreads();
    }
    if (t < nb) bs[t] = x - v;   // exclusive
}

__global__ void k_scan_add2(int* __restrict__ rpA, int* __restrict__ curA,
                            const int* __restrict__ bsA, int nA, int totA, int gA,
                            int* __restrict__ rpB, int* __restrict__ curB,
                            const int* __restrict__ bsB, int nB, int totB) {
    const bool isA = (blockIdx.x < (unsigned)gA);
    const int bid = isA ? blockIdx.x : blockIdx.x - gA;
    int* rowptr = isA ? rpA : rpB;
    int* cursor = isA ? curA : curB;
    const int* bsums = isA ? bsA : bsB;
    const int n = isA ? nA : nB;
    const int total = isA ? totA : totB;
    int i = bid * blockDim.x + threadIdx.x;
    if (i < n) {
        int f = rowptr[i] + bsums[i >> 11];
        rowptr[i] = f;
        cursor[i] = f;
    }
    if (i == 0) rowptr[n] = total;
}

// scatter + pack: write sorted edge records {gather_index, comp[et]*norm}
__global__ void k_scatter_pack(
    const int* __restrict__ dst1, const int* __restrict__ src1,
    const int* __restrict__ et1, const float* __restrict__ nrm1,
    const int* __restrict__ inodes, const float4* __restrict__ comp1,
    int* __restrict__ cur1, int* __restrict__ end1, float4* __restrict__ ew1,
    const int* __restrict__ dst2, const int* __restrict__ src2,
    const int* __restrict__ et2, const float* __restrict__ nrm2,
    const float4* __restrict__ comp2,
    int* __restrict__ cur2, int* __restrict__ end2, float4* __restrict__ ew2) {
    int i = blockIdx.x * blockDim.x + threadIdx.x;
    if (i < E1C) {
        int p = atomicAdd(&cur1[__ldg(dst1 + i)], 1);
        int nd = __ldg(inodes + __ldg(src1 + i));
        float n = __ldg(nrm1 + i);
        float4 c = __ldg(comp1 + __ldg(et1 + i));
        end1[p] = nd;
        ew1[p] = make_float4(c.x * n, c.y * n, c.z * n, c.w * n);
    } else if (i < E1C + E2C) {
        int e = i - E1C;
        int p = atomicAdd(&cur2[__ldg(dst2 + e)], 1);
        int nd = __ldg(src2 + e);
        float n = __ldg(nrm2 + e);
        float4 c = __ldg(comp2 + __ldg(et2 + e));
        end2[p] = nd;
        ew2[p] = make_float4(c.x * n, c.y * n, c.z * n, c.w * n);
    }
}

// ---------------- fused aggregate + project for one RGCN layer ----------------
// Phase A: 16 warps aggregate 8 dst rows each into smem z[128][258] (b-major).
// Phase B: C[128,OUTD] = z[128,256] @ W[256,OUTD] + bias (FFMA2, conflict-free).
template <int OUTD, bool RELU>
__global__ __launch_bounds__(512, 1)
void k_fused(const int* __restrict__ rowptr, const int* __restrict__ end,
             const float4* __restrict__ ew, const float* __restrict__ x,
             const float* __restrict__ W, const float* __restrict__ bias,
             float* __restrict__ out, int ndst) {
    constexpr int TM = 128, THREADS = 512, ZP = 258, H = OUTD / 2;
    constexpr int G = OUTD / 8;        // 8 (OUT=64) or 4 (OUT=32)
    constexpr int TYN = THREADS / G;   // 64 or 128
    constexpr int RPT = TM / TYN;      // 2 or 1

    extern __shared__ float sm[];
    float* Ws = sm;                    // [256*OUTD]
    float* zs = sm + 256 * OUTD;       // [TM][ZP]

    const int t = threadIdx.x;
    const int wp = t >> 5, lane = t & 31;
    const int rowbase = blockIdx.x * TM;

    // stage W once (K=256 rows, row-major)
    for (int i = t; i < 256 * OUTD / 4; i += THREADS)
        ((float4*)Ws)[i] = ((const float4*)W)[i];

    // ---- Phase A: aggregation into smem ----
#pragma unroll
    for (int j = 0; j < 8; j++) {
        const int row = wp * 8 + j;
        const int gr = rowbase + row;
        float2 a0 = {0.f, 0.f}, a1 = {0.f, 0.f}, a2 = {0.f, 0.f}, a3 = {0.f, 0.f};
        if (gr < ndst) {
            int p = __ldg(rowptr + gr);
            const int pe = __ldg(rowptr + gr + 1);
            for (; p + 4 <= pe; p += 4) {
                int n0 = __ldg(end + p), n1 = __ldg(end + p + 1);
                int n2 = __ldg(end + p + 2), n3 = __ldg(end + p + 3);
                float4 w0 = __ldg(ew + p), w1 = __ldg(ew + p + 1);
                float4 w2 = __ldg(ew + p + 2), w3 = __ldg(ew + p + 3);
                float2 x0 = __ldg((const float2*)(x + (size_t)n0 * 64) + lane);
                float2 x1 = __ldg((const float2*)(x + (size_t)n1 * 64) + lane);
                float2 x2 = __ldg((const float2*)(x + (size_t)n2 * 64) + lane);
                float2 x3 = __ldg((const float2*)(x + (size_t)n3 * 64) + lane);
                a0.x = fmaf(w0.x, x0.x, a0.x); a0.y = fmaf(w0.x, x0.y, a0.y);
                a1.x = fmaf(w0.y, x0.x, a1.x); a1.y = fmaf(w0.y, x0.y, a1.y);
                a2.x = fmaf(w0.z, x0.x, a2.x); a2.y = fmaf(w0.z, x0.y, a2.y);
                a3.x = fmaf(w0.w, x0.x, a3.x); a3.y = fmaf(w0.w, x0.y, a3.y);
                a0.x = fmaf(w1.x, x1.x, a0.x); a0.y = fmaf(w1.x, x1.y, a0.y);
                a1.x = fmaf(w1.y, x1.x, a1.x); a1.y = fmaf(w1.y, x1.y, a1.y);
                a2.x = fmaf(w1.z, x1.x, a2.x); a2.y = fmaf(w1.z, x1.y, a2.y);
                a3.x = fmaf(w1.w, x1.x, a3.x); a3.y = fmaf(w1.w, x1.y, a3.y);
                a0.x = fmaf(w2.x, x2.x, a0.x); a0.y = fmaf(w2.x, x2.y, a0.y);
                a1.x = fmaf(w2.y, x2.x, a1.x); a1.y = fmaf(w2.y, x2.y, a1.y);
                a2.x = fmaf(w2.z, x2.x, a2.x); a2.y = fmaf(w2.z, x2.y, a2.y);
                a3.x = fmaf(w2.w, x2.x, a3.x); a3.y = fmaf(w2.w, x2.y, a3.y);
                a0.x = fmaf(w3.x, x3.x, a0.x); a0.y = fmaf(w3.x, x3.y, a0.y);
                a1.x = fmaf(w3.y, x3.x, a1.x); a1.y = fmaf(w3.y, x3.y, a1.y);
                a2.x = fmaf(w3.z, x3.x, a2.x); a2.y = fmaf(w3.z, x3.y, a2.y);
                a3.x = fmaf(w3.w, x3.x, a3.x); a3.y = fmaf(w3.w, x3.y, a3.y);
            }
            for (; p < pe; p++) {
                int n0 = __ldg(end + p);
                float4 w0 = __ldg(ew + p);
                float2 x0 = __ldg((const float2*)(x + (size_t)n0 * 64) + lane);
                a0.x = fmaf(w0.x, x0.x, a0.x); a0.y = fmaf(w0.x, x0.y, a0.y);
                a1.x = fmaf(w0.y, x0.x, a1.x); a1.y = fmaf(w0.y, x0.y, a1.y);
                a2.x = fmaf(w0.z, x0.x, a2.x); a2.y = fmaf(w0.z, x0.y, a2.y);
                a3.x = fmaf(w0.w, x0.x, a3.x); a3.y = fmaf(w0.w, x0.y, a3.y);
            }
        }
        float2* zr = (float2*)(zs + row * ZP);   // k = b*64 + d (b-major, matches V flat)
        zr[lane]      = a0;
        zr[32 + lane] = a1;
        zr[64 + lane] = a2;
        zr[96 + lane] = a3;
    }
    __syncthreads();

    // ---- Phase B: projection GEMM ----
    const int tx = t % G;        // col groups: cols [4tx,4tx+4) and [H+4tx, H+4tx+4)
    const int ty = t / G;
    float2 acc[RPT][4];
#pragma unroll
    for (int r = 0; r < RPT; r++)
#pragma unroll
        for (int c = 0; c < 4; c++) acc[r][c] = make_float2(0.f, 0.f);

    const float* wb = Ws + tx * 4;
#pragma unroll 4
    for (int k = 0; k < 256; k += 2) {
        const float* wk = wb + k * OUTD;
        float4 wa0 = *(const float4*)(wk);
        float4 wb0 = *(const float4*)(wk + H);
        float4 wa1 = *(const float4*)(wk + OUTD);
        float4 wb1 = *(const float4*)(wk + OUTD + H);
#pragma unroll
        for (int r = 0; r < RPT; r++) {
            float2 zz = *(const float2*)(zs + (ty + r * TYN) * ZP + k);
            float2 zd0 = make_float2(zz.x, zz.x);
            float2 zd1 = make_float2(zz.y, zz.y);
            acc[r][0] = ffma2(zd0, make_float2(wa0.x, wa0.y), acc[r][0]);
            acc[r][1] = ffma2(zd0, make_float2(wa0.z, wa0.w), acc[r][1]);
            acc[r][2] = ffma2(zd0, make_float2(wb0.x, wb0.y), acc[r][2]);
            acc[r][3] = ffma2(zd0, make_float2(wb0.z, wb0.w), acc[r][3]);
            acc[r][0] = ffma2(zd1, make_float2(wa1.x, wa1.y), acc[r][0]);
            acc[r][1] = ffma2(zd1, make_float2(wa1.z, wa1.w), acc[r][1]);
            acc[r][2] = ffma2(zd1, make_float2(wb1.x, wb1.y), acc[r][2]);
            acc[r][3] = ffma2(zd1, make_float2(wb1.z, wb1.w), acc[r][3]);
        }
    }

    float4 bva = *(const float4*)(bias + tx * 4);
    float4 bvb = *(const float4*)(bias + H + tx * 4);
#pragma unroll
    for (int r = 0; r < RPT; r++) {
        int gr = rowbase + ty + r * TYN;
        if (gr < ndst) {
            float4 oA = make_float4(acc[r][0].x + bva.x, acc[r][0].y + bva.y,
                                    acc[r][1].x + bva.z, acc[r][1].y + bva.w);
            float4 oB = make_float4(acc[r][2].x + bvb.x, acc[r][2].y + bvb.y,
                                    acc[r][3].x + bvb.z, acc[r][3].y + bvb.w);
            if (RELU) {
                oA.x = fmaxf(oA.x, 0.f); oA.y = fmaxf(oA.y, 0.f);
                oA.z = fmaxf(oA.z, 0.f); oA.w = fmaxf(oA.w, 0.f);
                oB.x = fmaxf(oB.x, 0.f); oB.y = fmaxf(oB.y, 0.f);
                oB.z = fmaxf(oB.z, 0.f); oB.w = fmaxf(oB.w, 0.f);
            }
            *(float4*)(out + (size_t)gr * OUTD + tx * 4)     = oA;
            *(float4*)(out + (size_t)gr * OUTD + H + tx * 4) = oB;
        }
    }
}

// ---------------- host launcher ----------------
extern "C" void kernel_launch(void* const* d_in, const int* in_sizes, int n_in,
                              void* d_out, int out_size) {
    const int*   input_nodes = (const int*)d_in[0];
    const int*   src1  = (const int*)d_in[1];
    const int*   dst1  = (const int*)d_in[2];
    const int*   etyp1 = (const int*)d_in[3];
    const float* norm1 = (const float*)d_in[4];
    const int*   src2  = (const int*)d_in[5];
    const int*   dst2  = (const int*)d_in[6];
    const int*   etyp2 = (const int*)d_in[7];
    const float* norm2 = (const float*)d_in[8];
    const float* emb   = (const float*)d_in[9];
    const float* V1    = (const float*)d_in[10];
    const float* comp1 = (const float*)d_in[11];
    const float* b1    = (const float*)d_in[12];
    const float* V2    = (const float*)d_in[13];
    const float* comp2 = (const float*)d_in[14];
    const float* b2    = (const float*)d_in[15];
    float* out = (float*)d_out;

    void* p;
    int *rowptr1, *cursor1, *rowptr2, *cursor2, *bs1, *bs2, *end1, *end2;
    float4 *ew1, *ew2;
    float* h;
    cudaGetSymbolAddress(&p, g_rowptr1); rowptr1 = (int*)p;
    cudaGetSymbolAddress(&p, g_cursor1); cursor1 = (int*)p;
    cudaGetSymbolAddress(&p, g_rowptr2); rowptr2 = (int*)p;
    cudaGetSymbolAddress(&p, g_cursor2); cursor2 = (int*)p;
    cudaGetSymbolAddress(&p, g_bs1);     bs1     = (int*)p;
    cudaGetSymbolAddress(&p, g_bs2);     bs2     = (int*)p;
    cudaGetSymbolAddress(&p, g_end1);    end1    = (int*)p;
    cudaGetSymbolAddress(&p, g_ew1);     ew1     = (float4*)p;
    cudaGetSymbolAddress(&p, g_end2);    end2    = (int*)p;
    cudaGetSymbolAddress(&p, g_ew2);     ew2     = (float4*)p;
    cudaGetSymbolAddress(&p, g_h);       h       = (float*)p;

    const int smem1 = 256 * 64 * 4 + 128 * 258 * 4;   // 197632 B
    const int smem2 = 256 * 32 * 4 + 128 * 258 * 4;   // 164864 B
    cudaFuncSetAttribute(k_fused<64, true>,  cudaFuncAttributeMaxDynamicSharedMemorySize, smem1);
    cudaFuncSetAttribute(k_fused<32, false>, cudaFuncAttributeMaxDynamicSharedMemorySize, smem2);

    const int nb1 = (N1C + 2047) / 2048;   // 49
    const int nb2 = (N2C + 2047) / 2048;   // 10
    const int gA = (N1C + 255) / 256;      // 391
    const int gB = (N2C + 255) / 256;      // 79

    // --- counting sort by dst + edge packing (both layers) ---
    k_zero<<<(N1C + 256) / 256, 256>>>(cursor1, N1C, cursor2, N2C);
    k_hist<<<(E1C + E2C + 255) / 256, 256>>>(dst1, dst2, cursor1, cursor2);
    k_scan_local2<<<nb1 + nb2, 256>>>(cursor1, rowptr1, bs1, N1C, nb1,
                                      cursor2, rowptr2, bs2, N2C);
    k_scan_bsums2<<<2, 64>>>(bs1, nb1, bs2, nb2);
    k_scan_add2<<<gA + gB, 256>>>(rowptr1, cursor1, bs1, N1C, E1C, gA,
                                  rowptr2, cursor2, bs2, N2C, E2C);
    k_scatter_pack<<<(E1C + E2C + 255) / 256, 256>>>(
        dst1, src1, etyp1, norm1, input_nodes, (const float4*)comp1,
        cursor1, end1, ew1,
        dst2, src2, etyp2, norm2, (const float4*)comp2,
        cursor2, end2, ew2);

    // --- layer 1: fused aggregate + project (+ReLU) ---
    k_fused<64, true><<<(N1C + 127) / 128, 512, smem1>>>(
        rowptr1, end1, ew1, emb, V1, b1, h, N1C);

    // --- layer 2: fused aggregate + project ---
    k_fused<32, false><<<(N2C + 127) / 128, 512, smem2>>>(
        rowptr2, end2, ew2, h, V2, b2, out, N2C);
}

// round 6
// speedup vs baseline: 1.3341x; 1.3341x over previous
#include <cuda_runtime.h>
#include <cuda_bf16.h>
#include <cstdint>

// Problem constants
#define E1C   600000
#define E2C   300000
#define N1C   100000
#define N2C   20000

// ---------------- scratch (device globals; no allocation allowed) ----------------
__device__ int    g_rowptr1[N1C + 1];
__device__ int    g_cursor1[N1C + 1];
__device__ int    g_rowptr2[N2C + 1];
__device__ int    g_cursor2[N2C + 1];
__device__ int    g_bs1[64];
__device__ int    g_bs2[64];
__device__ int    g_end1[E1C];          // packed sorted: gather index
__device__ float4 g_ew1[E1C];           // packed sorted: comp[et]*norm per basis
__device__ int    g_end2[E2C];
__device__ float4 g_ew2[E2C];
__device__ float  g_z1[(size_t)N1C * 256];   // 102.4 MB
__device__ float  g_h [(size_t)N1C * 64];    // 25.6 MB
__device__ float  g_z2[(size_t)N2C * 256];   // 20.5 MB

// ---------------- packed f32x2 FMA (FFMA2 on sm_103a) ----------------
__device__ __forceinline__ float2 ffma2(float2 a, float2 b, float2 c) {
    float2 d;
    asm("fma.rn.f32x2 %0, %1, %2, %3;"
        : "=l"(reinterpret_cast<unsigned long long&>(d))
        : "l"(reinterpret_cast<unsigned long long&>(a)),
          "l"(reinterpret_cast<unsigned long long&>(b)),
          "l"(reinterpret_cast<unsigned long long&>(c)));
    return d;
}

// ---------------- counting-sort kernels ----------------
__global__ void k_zero(int* __restrict__ c1, int n1, int* __restrict__ c2, int n2) {
    int i = blockIdx.x * blockDim.x + threadIdx.x;
    if (i <= n1) c1[i] = 0;
    if (i <= n2) c2[i] = 0;
}

__global__ void k_hist(const int* __restrict__ dst1, const int* __restrict__ dst2,
                       int* __restrict__ c1, int* __restrict__ c2) {
    int i = blockIdx.x * blockDim.x + threadIdx.x;
    if (i < E1C) {
        atomicAdd(&c1[__ldg(dst1 + i)], 1);
    } else if (i < E1C + E2C) {
        atomicAdd(&c2[__ldg(dst2 + i - E1C)], 1);
    }
}

// per-block exclusive scan over 2048-element chunks; both layers in one launch
__global__ void k_scan_local2(const int* __restrict__ cntA, int* __restrict__ exclA,
                              int* __restrict__ bsA, int nA, int nbA,
                              const int* __restrict__ cntB, int* __restrict__ exclB,
                              int* __restrict__ bsB, int nB) {
    const int t = threadIdx.x;
    const bool isA = (blockIdx.x < (unsigned)nbA);
    const int bid = isA ? blockIdx.x : blockIdx.x - nbA;
    const int* cnt = isA ? cntA : cntB;
    int* excl = isA ? exclA : exclB;
    int* bsums = isA ? bsA : bsB;
    const int n = isA ? nA : nB;

    const int base = bid * 2048 + t * 8;
    int v[8], pre[8], s = 0;
#pragma unroll
    for (int j = 0; j < 8; j++) {
        int idx = base + j;
        v[j] = (idx < n) ? cnt[idx] : 0;
        pre[j] = s;
        s += v[j];
    }
    int lane = t & 31, wid = t >> 5;
    int inc = s;
#pragma unroll
    for (int off = 1; off < 32; off <<= 1) {
        int y = __shfl_up_sync(0xffffffffu, inc, off);
        if (lane >= off) inc += y;
    }
    __shared__ int wsum[8];
    __shared__ int wexcl[8];
    if (lane == 31) wsum[wid] = inc;
    __syncthreads();
    if (t == 0) {
        int run = 0;
        for (int w = 0; w < 8; w++) { wexcl[w] = run; run += wsum[w]; }
    }
    __syncthreads();
    int texcl = wexcl[wid] + inc - s;
#pragma unroll
    for (int j = 0; j < 8; j++) {
        int idx = base + j;
        if (idx < n) excl[idx] = texcl + pre[j];
    }
    if (t == 255) bsums[bid] = wexcl[7] + wsum[7];
}

// one block scans each bsums array (<=64 entries)
__global__ void k_scan_bsums2(int* __restrict__ bsA, int nA,
                              int* __restrict__ bsB, int nB) {
    __shared__ int sh[64];
    int t = threadIdx.x;
    int* bs = (blockIdx.x == 0) ? bsA : bsB;
    int nb  = (blockIdx.x == 0) ? nA : nB;
    int v = (t < nb) ? bs[t] : 0;
    int x = v;
    sh[t] = x;
    __syncthreads();
    for (int off = 1; off < 64; off <<= 1) {
        int y = (t >= off) ? sh[t - off] : 0;
        __syncthreads();
        x += y;
        sh[t] = x;
        __syncthreads();
    }
    if (t < nb) bs[t] = x - v;   // exclusive
}

__global__ void k_scan_add2(int* __restrict__ rpA, int* __restrict__ curA,
                            const int* __restrict__ bsA, int nA, int totA, int gA,
                            int* __restrict__ rpB, int* __restrict__ curB,
                            const int* __restrict__ bsB, int nB, int totB) {
    const bool isA = (blockIdx.x < (unsigned)gA);
    const int bid = isA ? blockIdx.x : blockIdx.x - gA;
    int* rowptr = isA ? rpA : rpB;
    int* cursor = isA ? curA : curB;
    const int* bsums = isA ? bsA : bsB;
    const int n = isA ? nA : nB;
    const int total = isA ? totA : totB;
    int i = bid * blockDim.x + threadIdx.x;
    if (i < n) {
        int f = rowptr[i] + bsums[i >> 11];
        rowptr[i] = f;
        cursor[i] = f;
    }
    if (i == 0) rowptr[n] = total;
}

// scatter + pack: write sorted edge records {gather_index, comp[et]*norm}
__global__ void k_scatter_pack(
    const int* __restrict__ dst1, const int* __restrict__ src1,
    const int* __restrict__ et1, const float* __restrict__ nrm1,
    const int* __restrict__ inodes, const float4* __restrict__ comp1,
    int* __restrict__ cur1, int* __restrict__ end1, float4* __restrict__ ew1,
    const int* __restrict__ dst2, const int* __restrict__ src2,
    const int* __restrict__ et2, const float* __restrict__ nrm2,
    const float4* __restrict__ comp2,
    int* __restrict__ cur2, int* __restrict__ end2, float4* __restrict__ ew2) {
    int i = blockIdx.x * blockDim.x + threadIdx.x;
    if (i < E1C) {
        int p = atomicAdd(&cur1[__ldg(dst1 + i)], 1);
        int nd = __ldg(inodes + __ldg(src1 + i));
        float n = __ldg(nrm1 + i);
        float4 c = __ldg(comp1 + __ldg(et1 + i));
        end1[p] = nd;
        ew1[p] = make_float4(c.x * n, c.y * n, c.z * n, c.w * n);
    } else if (i < E1C + E2C) {
        int e = i - E1C;
        int p = atomicAdd(&cur2[__ldg(dst2 + e)], 1);
        int nd = __ldg(src2 + e);
        float n = __ldg(nrm2 + e);
        float4 c = __ldg(comp2 + __ldg(et2 + e));
        end2[p] = nd;
        ew2[p] = make_float4(c.x * n, c.y * n, c.z * n, c.w * n);
    }
}

// ---------------- per-dst basis aggregation (one warp per dst, full occupancy) ----------------
// z[dst, b*64 + d] = sum_e ew_e[b] * x[end_e, d]
// lane owns dims {2*lane, 2*lane+1} for all 4 bases; packed sorted records,
// no atomics, no indirection chain. 4-deep gather batches for MLP.
__global__ void k_agg(const int* __restrict__ rowptr, const int* __restrict__ end,
                      const float4* __restrict__ ew, const float* __restrict__ x,
                      float* __restrict__ zout, int ndst) {
    int gw = (blockIdx.x * blockDim.x + threadIdx.x) >> 5;
    int lane = threadIdx.x & 31;
    if (gw >= ndst) return;

    float2 a0 = {0.f, 0.f}, a1 = {0.f, 0.f}, a2 = {0.f, 0.f}, a3 = {0.f, 0.f};
    int p = __ldg(rowptr + gw);
    const int pe = __ldg(rowptr + gw + 1);

    for (; p + 4 <= pe; p += 4) {
        int n0 = __ldg(end + p), n1 = __ldg(end + p + 1);
        int n2 = __ldg(end + p + 2), n3 = __ldg(end + p + 3);
        float4 w0 = __ldg(ew + p), w1 = __ldg(ew + p + 1);
        float4 w2 = __ldg(ew + p + 2), w3 = __ldg(ew + p + 3);
        float2 x0 = __ldg((const float2*)(x + (size_t)n0 * 64) + lane);
        float2 x1 = __ldg((const float2*)(x + (size_t)n1 * 64) + lane);
        float2 x2 = __ldg((const float2*)(x + (size_t)n2 * 64) + lane);
        float2 x3 = __ldg((const float2*)(x + (size_t)n3 * 64) + lane);
        a0.x = fmaf(w0.x, x0.x, a0.x); a0.y = fmaf(w0.x, x0.y, a0.y);
        a1.x = fmaf(w0.y, x0.x, a1.x); a1.y = fmaf(w0.y, x0.y, a1.y);
        a2.x = fmaf(w0.z, x0.x, a2.x); a2.y = fmaf(w0.z, x0.y, a2.y);
        a3.x = fmaf(w0.w, x0.x, a3.x); a3.y = fmaf(w0.w, x0.y, a3.y);
        a0.x = fmaf(w1.x, x1.x, a0.x); a0.y = fmaf(w1.x, x1.y, a0.y);
        a1.x = fmaf(w1.y, x1.x, a1.x); a1.y = fmaf(w1.y, x1.y, a1.y);
        a2.x = fmaf(w1.z, x1.x, a2.x); a2.y = fmaf(w1.z, x1.y, a2.y);
        a3.x = fmaf(w1.w, x1.x, a3.x); a3.y = fmaf(w1.w, x1.y, a3.y);
        a0.x = fmaf(w2.x, x2.x, a0.x); a0.y = fmaf(w2.x, x2.y, a0.y);
        a1.x = fmaf(w2.y, x2.x, a1.x); a1.y = fmaf(w2.y, x2.y, a1.y);
        a2.x = fmaf(w2.z, x2.x, a2.x); a2.y = fmaf(w2.z, x2.y, a2.y);
        a3.x = fmaf(w2.w, x2.x, a3.x); a3.y = fmaf(w2.w, x2.y, a3.y);
        a0.x = fmaf(w3.x, x3.x, a0.x); a0.y = fmaf(w3.x, x3.y, a0.y);
        a1.x = fmaf(w3.y, x3.x, a1.x); a1.y = fmaf(w3.y, x3.y, a1.y);
        a2.x = fmaf(w3.z, x3.x, a2.x); a2.y = fmaf(w3.z, x3.y, a2.y);
        a3.x = fmaf(w3.w, x3.x, a3.x); a3.y = fmaf(w3.w, x3.y, a3.y);
    }
    for (; p < pe; p++) {
        int n0 = __ldg(end + p);
        float4 w0 = __ldg(ew + p);
        float2 x0 = __ldg((const float2*)(x + (size_t)n0 * 64) + lane);
        a0.x = fmaf(w0.x, x0.x, a0.x); a0.y = fmaf(w0.x, x0.y, a0.y);
        a1.x = fmaf(w0.y, x0.x, a1.x); a1.y = fmaf(w0.y, x0.y, a1.y);
        a2.x = fmaf(w0.z, x0.x, a2.x); a2.y = fmaf(w0.z, x0.y, a2.y);
        a3.x = fmaf(w0.w, x0.x, a3.x); a3.y = fmaf(w0.w, x0.y, a3.y);
    }
    float2* zr = (float2*)(zout + (size_t)gw * 256);   // k = b*64+d (b-major = V flat)
    zr[lane]      = a0;
    zr[32 + lane] = a1;
    zr[64 + lane] = a2;
    zr[96 + lane] = a3;
}

// ---------------- dense projection GEMM: C[n,OUTD] = Z[n,256] @ W[256,OUTD] + bias ----------------
// FFMA2 inner kernel. z duplicated {z,z} at smem-store time so W column pairs
// load as natural f32x2 operands; (BK+1) padding keeps LDS conflict-free.
template <int OUTD, bool RELU>
__global__ void k_gemm(const float* __restrict__ Z, const float* __restrict__ W,
                       const float* __restrict__ bias, float* __restrict__ C, int nrows) {
    constexpr int K = 256, BK = 32;
    constexpr int G = OUTD / 4;       // col groups of 4
    constexpr int TY = 256 / G;       // 16 (OUT=64) or 32 (OUT=32)
    constexpr int ROWS = 8 * TY;      // 128 or 256 rows per block

    extern __shared__ float sm[];
    float*  Ws = sm;                                        // [K][OUTD]
    float2* zs = reinterpret_cast<float2*>(sm + K * OUTD);  // [ROWS][BK+1] duplicated

    const int t = threadIdx.x;
    const int tx = t % G;
    const int ty = t / G;
    const int rowbase = blockIdx.x * ROWS;

    // stage full W once
    for (int i = t; i < K * OUTD / 4; i += 256)
        ((float4*)Ws)[i] = ((const float4*)W)[i];

    float2 acc[8][2];
#pragma unroll
    for (int i = 0; i < 8; i++) { acc[i][0] = make_float2(0.f, 0.f); acc[i][1] = make_float2(0.f, 0.f); }

    for (int kb = 0; kb < K; kb += BK) {
        __syncthreads();
        constexpr int PASSES = ROWS / 32;
#pragma unroll
        for (int ps = 0; ps < PASSES; ps++) {
            int rl = ps * 32 + t / 8;
            int f4 = t % 8;
            int r = rowbase + rl;
            float4 zv = make_float4(0.f, 0.f, 0.f, 0.f);
            if (r < nrows) zv = *(const float4*)(Z + (size_t)r * K + kb + f4 * 4);
            float2* d = zs + rl * (BK + 1) + f4 * 4;
            d[0] = make_float2(zv.x, zv.x);
            d[1] = make_float2(zv.y, zv.y);
            d[2] = make_float2(zv.z, zv.z);
            d[3] = make_float2(zv.w, zv.w);
        }
        __syncthreads();
#pragma unroll
        for (int k = 0; k < BK; k++) {
            const float* wr = Ws + (kb + k) * OUTD + tx * 4;
            float2 w0 = *(const float2*)wr;
            float2 w1 = *(const float2*)(wr + 2);
#pragma unroll
            for (int i = 0; i < 8; i++) {
                float2 zd = zs[(i * TY + ty) * (BK + 1) + k];
                acc[i][0] = ffma2(zd, w0, acc[i][0]);
                acc[i][1] = ffma2(zd, w1, acc[i][1]);
            }
        }
    }

    float4 bv = *(const float4*)(bias + tx * 4);
#pragma unroll
    for (int i = 0; i < 8; i++) {
        int r = rowbase + i * TY + ty;
        if (r < nrows) {
            float4 o = make_float4(acc[i][0].x + bv.x, acc[i][0].y + bv.y,
                                   acc[i][1].x + bv.z, acc[i][1].y + bv.w);
            if (RELU) {
                o.x = fmaxf(o.x, 0.f); o.y = fmaxf(o.y, 0.f);
                o.z = fmaxf(o.z, 0.f); o.w = fmaxf(o.w, 0.f);
            }
            *(float4*)(C + (size_t)r * OUTD + tx * 4) = o;
        }
    }
}

// ---------------- host launcher ----------------
extern "C" void kernel_launch(void* const* d_in, const int* in_sizes, int n_in,
                              void* d_out, int out_size) {
    const int*   input_nodes = (const int*)d_in[0];
    const int*   src1  = (const int*)d_in[1];
    const int*   dst1  = (const int*)d_in[2];
    const int*   etyp1 = (const int*)d_in[3];
    const float* norm1 = (const float*)d_in[4];
    const int*   src2  = (const int*)d_in[5];
    const int*   dst2  = (const int*)d_in[6];
    const int*   etyp2 = (const int*)d_in[7];
    const float* norm2 = (const float*)d_in[8];
    const float* emb   = (const float*)d_in[9];
    const float* V1    = (const float*)d_in[10];
    const float* comp1 = (const float*)d_in[11];
    const float* b1    = (const float*)d_in[12];
    const float* V2    = (const float*)d_in[13];
    const float* comp2 = (const float*)d_in[14];
    const float* b2    = (const float*)d_in[15];
    float* out = (float*)d_out;

    void* p;
    int *rowptr1, *cursor1, *rowptr2, *cursor2, *bs1, *bs2, *end1, *end2;
    float4 *ew1, *ew2;
    float *z1, *h, *z2;
    cudaGetSymbolAddress(&p, g_rowptr1); rowptr1 = (int*)p;
    cudaGetSymbolAddress(&p, g_cursor1); cursor1 = (int*)p;
    cudaGetSymbolAddress(&p, g_rowptr2); rowptr2 = (int*)p;
    cudaGetSymbolAddress(&p, g_cursor2); cursor2 = (int*)p;
    cudaGetSymbolAddress(&p, g_bs1);     bs1     = (int*)p;
    cudaGetSymbolAddress(&p, g_bs2);     bs2     = (int*)p;
    cudaGetSymbolAddress(&p, g_end1);    end1    = (int*)p;
    cudaGetSymbolAddress(&p, g_ew1);     ew1     = (float4*)p;
    cudaGetSymbolAddress(&p, g_end2);    end2    = (int*)p;
    cudaGetSymbolAddress(&p, g_ew2);     ew2     = (float4*)p;
    cudaGetSymbolAddress(&p, g_z1);      z1      = (float*)p;
    cudaGetSymbolAddress(&p, g_h);       h       = (float*)p;
    cudaGetSymbolAddress(&p, g_z2);      z2      = (float*)p;

    const int smem1 = 256 * 64 * 4 + 128 * 33 * 8;   // 99328 B
    const int smem2 = 256 * 32 * 4 + 256 * 33 * 8;   // 100352 B
    cudaFuncSetAttribute(k_gemm<64, true>,  cudaFuncAttributeMaxDynamicSharedMemorySize, smem1);
    cudaFuncSetAttribute(k_gemm<32, false>, cudaFuncAttributeMaxDynamicSharedMemorySize, smem2);

    const int nb1 = (N1C + 2047) / 2048;   // 49
    const int nb2 = (N2C + 2047) / 2048;   // 10
    const int gA = (N1C + 255) / 256;      // 391
    const int gB = (N2C + 255) / 256;      // 79

    // --- counting sort by dst + edge packing (both layers) ---
    k_zero<<<(N1C + 256) / 256, 256>>>(cursor1, N1C, cursor2, N2C);
    k_hist<<<(E1C + E2C + 255) / 256, 256>>>(dst1, dst2, cursor1, cursor2);
    k_scan_local2<<<nb1 + nb2, 256>>>(cursor1, rowptr1, bs1, N1C, nb1,
                                      cursor2, rowptr2, bs2, N2C);
    k_scan_bsums2<<<2, 64>>>(bs1, nb1, bs2, nb2);
    k_scan_add2<<<gA + gB, 256>>>(rowptr1, cursor1, bs1, N1C, E1C, gA,
                                  rowptr2, cursor2, bs2, N2C, E2C);
    k_scatter_pack<<<(E1C + E2C + 255) / 256, 256>>>(
        dst1, src1, etyp1, norm1, input_nodes, (const float4*)comp1,
        cursor1, end1, ew1,
        dst2, src2, etyp2, norm2, (const float4*)comp2,
        cursor2, end2, ew2);

    // --- layer 1: aggregate (full occupancy) -> project (FFMA2 GEMM) ---
    k_agg<<<(N1C * 32 + 255) / 256, 256>>>(rowptr1, end1, ew1, emb, z1, N1C);
    k_gemm<64, true><<<(N1C + 127) / 128, 256, smem1>>>(z1, V1, b1, h, N1C);

    // --- layer 2 ---
    k_agg<<<(N2C * 32 + 255) / 256, 256>>>(rowptr2, end2, ew2, h, z2, N2C);
    k_gemm<32, false><<<(N2C + 255) / 256, 256, smem2>>>(z2, V2, b2, out, N2C);
}